// round 7
// baseline (speedup 1.0000x reference)
#include <cuda_runtime.h>
#include <cuda_bf16.h>
#include <mma.h>
#include <math.h>
#include <stdint.h>

// ---------------- problem constants ----------------
#define BZ    8
#define HH    56
#define WW    56
#define HWP   3136
#define RR    25088       // BZ*HWP rows
#define C0N   256
#define C1N   512
#define C2N   1024
#define CIN   1794
#define DOUT  448
#define NC    3136

#define KBP   1856        // gemmB K padded (29*64)
#define XSTR  (2*KBP)     // hi plane + lo plane
#define KCP   448         // gemmC K (7*64)
#define PSTR  (2*KCP)

#define SEG_B (KBP/64)    // 29
#define SEG_C (KCP/64)    // 7
#define NCH_B (3*SEG_B)   // 87
#define NCH_C (3*SEG_C)   // 21

// smem layout (bytes) — total 93,952 => 2 CTAs/SM
#define A0OF  0           // 128x72 bf16 = 18432
#define A1OF  18432
#define B0OF  36864       // 64x72 bf16 = 9216
#define B1OF  46080
#define CSOF  55296       // 128x72 f32 = 36864
#define AUX1  92160       // 64 floats: bias / cent2 tile
#define AUX2  92416       // 128*3 floats: sfeat / trip
#define SMEM_SZ 93952

// ---------------- scratch ----------------
__device__ float g_pool1[BZ * C1N * 28 * 28];
__device__ float g_pool2[BZ * C2N * 14 * 14];
__device__ float g_feat2[RR];
__device__ float g_cent2[NC];
__device__ __align__(16) unsigned short gXt[(size_t)RR * XSTR];
__device__ __align__(16) unsigned short gWt[(size_t)DOUT * XSTR];
__device__ __align__(16) unsigned short gPhiT[(size_t)RR * PSTR];
__device__ __align__(16) unsigned short gCt[(size_t)NC * PSTR];

// ---------------- helpers ----------------
__device__ __forceinline__ unsigned short f2bf(float x) {
    __nv_bfloat16 h = __float2bfloat16(x);
    unsigned short u; memcpy(&u, &h, 2); return u;
}
__device__ __forceinline__ float bf2f(unsigned short u) {
    __nv_bfloat16 h; memcpy(&h, &u, 2); return __bfloat162float(h);
}
__device__ __forceinline__ void ins3(float v, float& a, float& b, float& c) {
    if (v < c) {
        if (v < b) { c = b; if (v < a) { b = a; a = v; } else b = v; }
        else c = v;
    }
}
__device__ __forceinline__ float bilin(const float* __restrict__ ch, int S, float u, float v) {
    int y0 = (int)floorf(u); float fy = u - (float)y0;
    int x0 = (int)floorf(v); float fx = v - (float)x0;
    int y0c = min(max(y0, 0), S - 1);
    int y1c = min(max(y0 + 1, 0), S - 1);
    int x0c = min(max(x0, 0), S - 1);
    int x1c = min(max(x0 + 1, 0), S - 1);
    float a = ch[y0c * S + x0c], b = ch[y0c * S + x1c];
    float c = ch[y1c * S + x0c], d = ch[y1c * S + x1c];
    return (1.f - fy) * ((1.f - fx) * a + fx * b) + fy * ((1.f - fx) * c + fx * d);
}

// stage NROWS x 64 bf16 into padded stride-72 smem (LDG+STS, R4-proven)
template<int NROWS>
__device__ __forceinline__ void fstage(const unsigned short* __restrict__ src,
                                       size_t rstride, unsigned short* dst, int tid) {
    #pragma unroll
    for (int s = 0; s < NROWS * 8 / 256; s++) {
        int l = tid + s * 256;
        int row = l >> 3, c8 = l & 7;
        uint4 v = *(const uint4*)(src + (size_t)row * rstride + c8 * 8);
        *(uint4*)(dst + row * 72 + c8 * 8) = v;
    }
}

// ---------------- stage 1: pools for p1/p2 ----------------
__global__ void pool_kernel(const float* __restrict__ in, int total, int S, int which) {
    int idx = blockIdx.x * 256 + threadIdx.x;
    if (idx >= total) return;
    int x = idx % S, y = (idx / S) % S, bc = idx / (S * S);
    const float* p = in + (size_t)bc * S * S;
    float s = 0.f;
    #pragma unroll
    for (int dy = -1; dy <= 1; dy++) {
        int yy = y + dy; if ((unsigned)yy >= (unsigned)S) continue;
        #pragma unroll
        for (int dx = -1; dx <= 1; dx++) {
            int xx = x + dx; if ((unsigned)xx >= (unsigned)S) continue;
            s += p[yy * S + xx];
        }
    }
    (which ? g_pool2 : g_pool1)[idx] = s * (1.f / 9.f);
}

// ---------------- stage 2: weight/center packing ----------------
__global__ void prepW_kernel(const float* __restrict__ w) {
    int idx = blockIdx.x * 256 + threadIdx.x;
    if (idx >= DOUT * KBP) return;
    int o = idx / KBP, k = idx - o * KBP;
    float v = (k < CIN) ? w[o * CIN + k] : 0.f;
    unsigned short h = f2bf(v);
    gWt[(size_t)o * XSTR + k] = h;
    gWt[(size_t)o * XSTR + KBP + k] = f2bf(v - bf2f(h));
}

__global__ void prepC_kernel(const float* __restrict__ Cmat) {
    int idx = blockIdx.x * 256 + threadIdx.x;
    if (idx >= NC * KCP) return;
    int k = idx / NC, n = idx - k * NC;
    float v = Cmat[(size_t)k * NC + n];
    unsigned short h = f2bf(v);
    gCt[(size_t)n * PSTR + k] = h;
    gCt[(size_t)n * PSTR + KCP + k] = f2bf(v - bf2f(h));
}

__global__ void cent2_kernel(const float* __restrict__ Cmat) {
    int gid = blockIdx.x * 256 + threadIdx.x;
    int n = gid >> 3, part = gid & 7;
    if (n >= NC) return;
    float s = 0.f;
    for (int o = part; o < DOUT; o += 8) {
        float v = Cmat[(size_t)o * NC + n];
        s = fmaf(v, v, s);
    }
    s += __shfl_xor_sync(0xFFFFFFFFu, s, 1);
    s += __shfl_xor_sync(0xFFFFFFFFu, s, 2);
    s += __shfl_xor_sync(0xFFFFFFFFu, s, 4);
    if (part == 0) g_cent2[n] = s;
}

// ---------------- stage 3: build X row-major bf16 hi/lo via smem transpose ----------------
__global__ void buildx_kernel(const float* __restrict__ p0) {
    __shared__ float s[64][65];
    int rt0 = blockIdx.x * 64;
    int kt0 = blockIdx.y * 64;
    int tid = threadIdx.x;
    int rr = tid & 63;
    int r = rt0 + rr;
    int b = r / HWP;
    int pix = r - b * HWP;
    int h = pix / WW, w = pix - h * WW;

    #pragma unroll 1
    for (int i = 0; i < 16; i++) {
        int kk = (tid >> 6) * 16 + i;
        int k = kt0 + kk;
        float val;
        if (k < C0N) {
            const float* p = p0 + (size_t)(b * C0N + k) * HWP;
            float acc = 0.f;
            #pragma unroll
            for (int dy = -1; dy <= 1; dy++) {
                int y = h + dy; if ((unsigned)y >= (unsigned)HH) continue;
                #pragma unroll
                for (int dx = -1; dx <= 1; dx++) {
                    int x = w + dx; if ((unsigned)x >= (unsigned)WW) continue;
                    acc += p[y * WW + x];
                }
            }
            val = acc * (1.f / 9.f);
        } else if (k < C0N + C1N) {
            const float* ch = g_pool1 + (size_t)(b * C1N + (k - C0N)) * 784;
            val = bilin(ch, 28, h * 0.5f - 0.25f, w * 0.5f - 0.25f);
        } else if (k < C0N + C1N + C2N) {
            const float* ch = g_pool2 + (size_t)(b * C2N + (k - C0N - C1N)) * 196;
            val = bilin(ch, 14, h * 0.25f - 0.375f, w * 0.25f - 0.375f);
        } else if (k == 1792) {
            val = (float)h * (2.f / 55.f) - 1.f;
        } else if (k == 1793) {
            val = (float)w * (2.f / 55.f) - 1.f;
        } else {
            val = 0.f;
        }
        s[kk][rr] = val;
    }
    __syncthreads();

    #pragma unroll
    for (int it = 0; it < 2; it++) {
        int sg = tid + it * 256;
        int row = sg >> 3, c8 = (sg & 7) * 8;
        unsigned hw[4], lw[4];
        #pragma unroll
        for (int j = 0; j < 8; j += 2) {
            float v0 = s[c8 + j][row], v1 = s[c8 + j + 1][row];
            unsigned short h0 = f2bf(v0), h1 = f2bf(v1);
            unsigned short l0 = f2bf(v0 - bf2f(h0)), l1 = f2bf(v1 - bf2f(h1));
            hw[j >> 1] = (unsigned)h0 | ((unsigned)h1 << 16);
            lw[j >> 1] = (unsigned)l0 | ((unsigned)l1 << 16);
        }
        size_t base = (size_t)(rt0 + row) * XSTR + kt0 + c8;
        *(uint4*)(gXt + base)       = make_uint4(hw[0], hw[1], hw[2], hw[3]);
        *(uint4*)(gXt + base + KBP) = make_uint4(lw[0], lw[1], lw[2], lw[3]);
    }
}

// ==================================================================
// GEMM-B: phi = X * W^T + bias; fused feat2 + bf16 hi/lo store.
// block 128x64, 8 warps 4m x 2n, warp tile 32x32, 2 CTAs/SM.
// ==================================================================
__global__ void __launch_bounds__(256, 2)
gemmB_kernel(const float* __restrict__ bias) {
    using namespace nvcuda;
    extern __shared__ char smc[];
    unsigned short* Ab[2] = {(unsigned short*)(smc + A0OF), (unsigned short*)(smc + A1OF)};
    unsigned short* Bb[2] = {(unsigned short*)(smc + B0OF), (unsigned short*)(smc + B1OF)};
    float* Cs = (float*)(smc + CSOF);
    float* biasS = (float*)(smc + AUX1);
    float* sfeat = (float*)(smc + AUX2);
    int tid = threadIdx.x, wid = tid >> 5;
    int wm = wid & 3, wn = wid >> 2;
    int r0 = blockIdx.x * 128;
    int erow = tid >> 1, ehalf = tid & 1;
    float feat_acc = 0.f;

    #pragma unroll 1
    for (int nt = 0; nt < DOUT / 64; nt++) {
        if (tid < 64) biasS[tid] = bias[nt * 64 + tid];

        wmma::fragment<wmma::accumulator, 16, 16, 16, float> acc[2][2];
        #pragma unroll
        for (int mi = 0; mi < 2; mi++)
            #pragma unroll
            for (int nj = 0; nj < 2; nj++) wmma::fill_fragment(acc[mi][nj], 0.f);

        auto stage = [&](int c, int buf) {
            int seg = c / SEG_B;
            int kb = (c - seg * SEG_B) * 64;
            int pa = (seg == 2) ? KBP : 0;
            int pb = (seg == 1) ? KBP : 0;
            fstage<128>(gXt + (size_t)r0 * XSTR + pa + kb, XSTR, Ab[buf], tid);
            fstage<64>(gWt + (size_t)(nt * 64) * XSTR + pb + kb, XSTR, Bb[buf], tid);
        };

        stage(0, 0);
        __syncthreads();

        #pragma unroll 1
        for (int c = 0; c < NCH_B; c++) {
            int buf = c & 1;
            if (c + 1 < NCH_B) stage(c + 1, buf ^ 1);
            const __nv_bfloat16* Ap = (const __nv_bfloat16*)Ab[buf];
            const __nv_bfloat16* Bp = (const __nv_bfloat16*)Bb[buf];
            #pragma unroll
            for (int ks = 0; ks < 4; ks++) {
                wmma::fragment<wmma::matrix_b, 16, 16, 16, __nv_bfloat16, wmma::col_major> bf[2];
                wmma::load_matrix_sync(bf[0], Bp + (wn * 32) * 72 + ks * 16, 72);
                wmma::load_matrix_sync(bf[1], Bp + (wn * 32 + 16) * 72 + ks * 16, 72);
                #pragma unroll
                for (int mi = 0; mi < 2; mi++) {
                    wmma::fragment<wmma::matrix_a, 16, 16, 16, __nv_bfloat16, wmma::row_major> af;
                    wmma::load_matrix_sync(af, Ap + (wm * 32 + mi * 16) * 72 + ks * 16, 72);
                    wmma::mma_sync(acc[mi][0], af, bf[0], acc[mi][0]);
                    wmma::mma_sync(acc[mi][1], af, bf[1], acc[mi][1]);
                }
            }
            __syncthreads();
        }

        // epilogue through block C tile
        #pragma unroll
        for (int mi = 0; mi < 2; mi++)
            #pragma unroll
            for (int nj = 0; nj < 2; nj++)
                wmma::store_matrix_sync(Cs + (wm * 32 + mi * 16) * 72 + wn * 32 + nj * 16,
                                        acc[mi][nj], 72, wmma::mem_row_major);
        __syncthreads();

        {
            const float* crow = Cs + erow * 72 + ehalf * 32;
            const float* brow = biasS + ehalf * 32;
            size_t r = (size_t)r0 + erow;
            int col0 = nt * 64 + ehalf * 32;
            unsigned hw[16], lw[16];
            #pragma unroll
            for (int j = 0; j < 32; j += 2) {
                float v0 = crow[j] + brow[j];
                float v1 = crow[j + 1] + brow[j + 1];
                feat_acc = fmaf(v0, v0, feat_acc);
                feat_acc = fmaf(v1, v1, feat_acc);
                unsigned short h0 = f2bf(v0), h1 = f2bf(v1);
                unsigned short l0 = f2bf(v0 - bf2f(h0)), l1 = f2bf(v1 - bf2f(h1));
                hw[j >> 1] = (unsigned)h0 | ((unsigned)h1 << 16);
                lw[j >> 1] = (unsigned)l0 | ((unsigned)l1 << 16);
            }
            uint4* dh = (uint4*)(gPhiT + r * PSTR + col0);
            uint4* dl = (uint4*)(gPhiT + r * PSTR + KCP + col0);
            #pragma unroll
            for (int q = 0; q < 4; q++) {
                dh[q] = make_uint4(hw[q * 4], hw[q * 4 + 1], hw[q * 4 + 2], hw[q * 4 + 3]);
                dl[q] = make_uint4(lw[q * 4], lw[q * 4 + 1], lw[q * 4 + 2], lw[q * 4 + 3]);
            }
        }
        __syncthreads();
    }

    if (ehalf == 0) sfeat[erow] = feat_acc;
    __syncthreads();
    if (ehalf == 1) g_feat2[r0 + erow] = sfeat[erow] + feat_acc;
}

// ==================================================================
// GEMM-C: streaming top-3 over 49 center tiles of 64; softmin score.
// block 128x64, 8 warps 4m x 2n, warp tile 32x32, 2 CTAs/SM.
// ==================================================================
__global__ void __launch_bounds__(256, 2)
gemmC_kernel(float* __restrict__ out) {
    using namespace nvcuda;
    extern __shared__ char smc[];
    unsigned short* Ab[2] = {(unsigned short*)(smc + A0OF), (unsigned short*)(smc + A1OF)};
    unsigned short* Bb[2] = {(unsigned short*)(smc + B0OF), (unsigned short*)(smc + B1OF)};
    float* Cs = (float*)(smc + CSOF);
    float* c2S = (float*)(smc + AUX1);
    float* trip = (float*)(smc + AUX2);
    int tid = threadIdx.x, wid = tid >> 5;
    int wm = wid & 3, wn = wid >> 2;
    int r0 = blockIdx.x * 128;
    int erow = tid >> 1, ehalf = tid & 1;

    const float BIG = 3.4e38f;
    float t0 = BIG, t1 = BIG, t2 = BIG;

    #pragma unroll 1
    for (int nt = 0; nt < NC / 64; nt++) {
        if (tid < 64) c2S[tid] = g_cent2[nt * 64 + tid];

        wmma::fragment<wmma::accumulator, 16, 16, 16, float> acc[2][2];
        #pragma unroll
        for (int mi = 0; mi < 2; mi++)
            #pragma unroll
            for (int nj = 0; nj < 2; nj++) wmma::fill_fragment(acc[mi][nj], 0.f);

        auto stage = [&](int c, int buf) {
            int seg = c / SEG_C;
            int kb = (c - seg * SEG_C) * 64;
            int pa = (seg == 2) ? KCP : 0;
            int pb = (seg == 1) ? KCP : 0;
            fstage<128>(gPhiT + (size_t)r0 * PSTR + pa + kb, PSTR, Ab[buf], tid);
            fstage<64>(gCt + (size_t)(nt * 64) * PSTR + pb + kb, PSTR, Bb[buf], tid);
        };

        stage(0, 0);
        __syncthreads();

        #pragma unroll 1
        for (int c = 0; c < NCH_C; c++) {
            int buf = c & 1;
            if (c + 1 < NCH_C) stage(c + 1, buf ^ 1);
            const __nv_bfloat16* Ap = (const __nv_bfloat16*)Ab[buf];
            const __nv_bfloat16* Bp = (const __nv_bfloat16*)Bb[buf];
            #pragma unroll
            for (int ks = 0; ks < 4; ks++) {
                wmma::fragment<wmma::matrix_b, 16, 16, 16, __nv_bfloat16, wmma::col_major> bf[2];
                wmma::load_matrix_sync(bf[0], Bp + (wn * 32) * 72 + ks * 16, 72);
                wmma::load_matrix_sync(bf[1], Bp + (wn * 32 + 16) * 72 + ks * 16, 72);
                #pragma unroll
                for (int mi = 0; mi < 2; mi++) {
                    wmma::fragment<wmma::matrix_a, 16, 16, 16, __nv_bfloat16, wmma::row_major> af;
                    wmma::load_matrix_sync(af, Ap + (wm * 32 + mi * 16) * 72 + ks * 16, 72);
                    wmma::mma_sync(acc[mi][0], af, bf[0], acc[mi][0]);
                    wmma::mma_sync(acc[mi][1], af, bf[1], acc[mi][1]);
                }
            }
            __syncthreads();
        }

        #pragma unroll
        for (int mi = 0; mi < 2; mi++)
            #pragma unroll
            for (int nj = 0; nj < 2; nj++)
                wmma::store_matrix_sync(Cs + (wm * 32 + mi * 16) * 72 + wn * 32 + nj * 16,
                                        acc[mi][nj], 72, wmma::mem_row_major);
        __syncthreads();

        {
            const float* crow = Cs + erow * 72 + ehalf * 32;
            const float* c2p = c2S + ehalf * 32;
            #pragma unroll
            for (int j = 0; j < 32; j++) {
                float key = c2p[j] - 2.f * crow[j];
                ins3(key, t0, t1, t2);
            }
        }
        __syncthreads();
    }

    // merge halves
    if (ehalf == 0) {
        trip[erow * 3 + 0] = t0;
        trip[erow * 3 + 1] = t1;
        trip[erow * 3 + 2] = t2;
    }
    __syncthreads();
    if (ehalf == 1) {
        ins3(trip[erow * 3 + 0], t0, t1, t2);
        ins3(trip[erow * 3 + 1], t0, t1, t2);
        ins3(trip[erow * 3 + 2], t0, t1, t2);
        float f2 = g_feat2[r0 + erow];
        float d0 = sqrtf(fmaxf(f2 + t0, 0.f));
        float d1 = sqrtf(fmaxf(f2 + t1, 0.f));
        float d2 = sqrtf(fmaxf(f2 + t2, 0.f));
        float s = 1.f / (1.f + expf(d0 - d1) + expf(d0 - d2));
        out[r0 + erow] = d0 * s;
    }
}

// ---------------- launch ----------------
extern "C" void kernel_launch(void* const* d_in, const int* in_sizes, int n_in,
                              void* d_out, int out_size) {
    (void)in_sizes; (void)n_in; (void)out_size;
    const float* p0     = (const float*)d_in[0];
    const float* p1     = (const float*)d_in[1];
    const float* p2     = (const float*)d_in[2];
    const float* conv_w = (const float*)d_in[3];
    const float* conv_b = (const float*)d_in[4];
    const float* Cmat   = (const float*)d_in[5];
    float* out = (float*)d_out;

    {
        int t1 = BZ * C1N * 28 * 28;
        pool_kernel<<<(t1 + 255) / 256, 256>>>(p1, t1, 28, 0);
        int t2 = BZ * C2N * 14 * 14;
        pool_kernel<<<(t2 + 255) / 256, 256>>>(p2, t2, 14, 1);
    }
    prepW_kernel<<<(DOUT * KBP + 255) / 256, 256>>>(conv_w);
    prepC_kernel<<<(NC * KCP + 255) / 256, 256>>>(Cmat);
    cent2_kernel<<<(NC * 8 + 255) / 256, 256>>>(Cmat);
    {
        dim3 grid(RR / 64, KBP / 64);
        buildx_kernel<<<grid, 256>>>(p0);
    }
    {
        cudaFuncSetAttribute(gemmB_kernel, cudaFuncAttributeMaxDynamicSharedMemorySize, SMEM_SZ);
        gemmB_kernel<<<RR / 128, 256, SMEM_SZ>>>(conv_b);
    }
    {
        cudaFuncSetAttribute(gemmC_kernel, cudaFuncAttributeMaxDynamicSharedMemorySize, SMEM_SZ);
        gemmC_kernel<<<RR / 128, 256, SMEM_SZ>>>(out);
    }
}

// round 8
// speedup vs baseline: 1.7803x; 1.7803x over previous
#include <cuda_runtime.h>
#include <cuda_bf16.h>
#include <mma.h>
#include <math.h>
#include <stdint.h>

// ---------------- problem constants ----------------
#define BZ    8
#define HH    56
#define WW    56
#define HWP   3136
#define RR    25088       // BZ*HWP rows
#define C0N   256
#define C1N   512
#define C2N   1024
#define CIN   1794
#define DOUT  448
#define NC    3136

#define KBP   1856        // gemmB K padded (29*64)
#define XSTR  (2*KBP)     // hi plane + lo plane
#define KCP   448         // gemmC K (7*64)
#define PSTR  (2*KCP)

#define SEG_B (KBP/64)    // 29
#define SEG_C (KCP/64)    // 7
#define NCH_B (3*SEG_B)   // 87
#define NCH_C (3*SEG_C)   // 21

// smem layout (bytes)
#define A0OF  0           // 128x72 bf16 = 18432
#define A1OF  18432
#define B0OF  36864       // 64x72 bf16 = 9216
#define B1OF  46080
#define CSOF  55296       // 128x72 f32 = 36864
#define AUX1  92160       // 64 floats: bias / cent2 tile
#define AUX2  92416       // 128*3 floats: sfeat / trip
#define SMEM_SZ 93952

// ---------------- scratch ----------------
__device__ float g_pool1[BZ * C1N * 28 * 28];
__device__ float g_pool2[BZ * C2N * 14 * 14];
__device__ float g_feat2[RR];
__device__ float g_cent2[NC];
__device__ __align__(16) unsigned short gXt[(size_t)RR * XSTR];
__device__ __align__(16) unsigned short gWt[(size_t)DOUT * XSTR];
__device__ __align__(16) unsigned short gPhiT[(size_t)RR * PSTR];
__device__ __align__(16) unsigned short gCt[(size_t)NC * PSTR];

// ---------------- helpers ----------------
__device__ __forceinline__ uint32_t smem_u32(const void* p) {
    uint32_t a;
    asm("{ .reg .u64 t; cvta.to.shared.u64 t, %1; cvt.u32.u64 %0, t; }" : "=r"(a) : "l"(p));
    return a;
}
__device__ __forceinline__ void cp16(uint32_t dst, const void* src) {
    asm volatile("cp.async.cg.shared.global [%0], [%1], 16;" :: "r"(dst), "l"(src) : "memory");
}
#define CP_COMMIT() asm volatile("cp.async.commit_group;" ::: "memory")
#define CP_WAIT1()  asm volatile("cp.async.wait_group 1;" ::: "memory")
#define CP_WAIT0()  asm volatile("cp.async.wait_group 0;" ::: "memory")

__device__ __forceinline__ unsigned short f2bf(float x) {
    __nv_bfloat16 h = __float2bfloat16(x);
    unsigned short u; memcpy(&u, &h, 2); return u;
}
__device__ __forceinline__ float bf2f(unsigned short u) {
    __nv_bfloat16 h; memcpy(&h, &u, 2); return __bfloat162float(h);
}
__device__ __forceinline__ void ins3(float v, float& a, float& b, float& c) {
    if (v < c) {
        if (v < b) { c = b; if (v < a) { b = a; a = v; } else b = v; }
        else c = v;
    }
}
__device__ __forceinline__ float bilin(const float* __restrict__ ch, int S, float u, float v) {
    int y0 = (int)floorf(u); float fy = u - (float)y0;
    int x0 = (int)floorf(v); float fx = v - (float)x0;
    int y0c = min(max(y0, 0), S - 1);
    int y1c = min(max(y0 + 1, 0), S - 1);
    int x0c = min(max(x0, 0), S - 1);
    int x1c = min(max(x0 + 1, 0), S - 1);
    float a = ch[y0c * S + x0c], b = ch[y0c * S + x1c];
    float c = ch[y1c * S + x0c], d = ch[y1c * S + x1c];
    return (1.f - fy) * ((1.f - fx) * a + fx * b) + fy * ((1.f - fx) * c + fx * d);
}

// async-stage NROWS x 64 bf16 into padded stride-72 smem
template<int NROWS>
__device__ __forceinline__ void astage(const unsigned short* __restrict__ src,
                                       size_t rstride, uint32_t dst, int tid) {
    #pragma unroll
    for (int s = 0; s < NROWS * 8 / 256; s++) {
        int l = tid + s * 256;
        int row = l >> 3, c8 = l & 7;
        cp16(dst + row * 144 + c8 * 16, src + (size_t)row * rstride + c8 * 8);
    }
}

// ---------------- stage 1: pools for p1/p2 ----------------
__global__ void pool_kernel(const float* __restrict__ in, int total, int S, int which) {
    int idx = blockIdx.x * 256 + threadIdx.x;
    if (idx >= total) return;
    int x = idx % S, y = (idx / S) % S, bc = idx / (S * S);
    const float* p = in + (size_t)bc * S * S;
    float s = 0.f;
    #pragma unroll
    for (int dy = -1; dy <= 1; dy++) {
        int yy = y + dy; if ((unsigned)yy >= (unsigned)S) continue;
        #pragma unroll
        for (int dx = -1; dx <= 1; dx++) {
            int xx = x + dx; if ((unsigned)xx >= (unsigned)S) continue;
            s += p[yy * S + xx];
        }
    }
    (which ? g_pool2 : g_pool1)[idx] = s * (1.f / 9.f);
}

// ---------------- stage 2: weight/center packing ----------------
__global__ void prepW_kernel(const float* __restrict__ w) {
    int idx = blockIdx.x * 256 + threadIdx.x;
    if (idx >= DOUT * KBP) return;
    int o = idx / KBP, k = idx - o * KBP;
    float v = (k < CIN) ? w[o * CIN + k] : 0.f;
    unsigned short h = f2bf(v);
    gWt[(size_t)o * XSTR + k] = h;
    gWt[(size_t)o * XSTR + KBP + k] = f2bf(v - bf2f(h));
}

__global__ void prepC_kernel(const float* __restrict__ Cmat) {
    int idx = blockIdx.x * 256 + threadIdx.x;
    if (idx >= NC * KCP) return;
    int k = idx / NC, n = idx - k * NC;
    float v = Cmat[(size_t)k * NC + n];
    unsigned short h = f2bf(v);
    gCt[(size_t)n * PSTR + k] = h;
    gCt[(size_t)n * PSTR + KCP + k] = f2bf(v - bf2f(h));
}

__global__ void cent2_kernel(const float* __restrict__ Cmat) {
    int gid = blockIdx.x * 256 + threadIdx.x;
    int n = gid >> 3, part = gid & 7;
    if (n >= NC) return;
    float s = 0.f;
    for (int o = part; o < DOUT; o += 8) {
        float v = Cmat[(size_t)o * NC + n];
        s = fmaf(v, v, s);
    }
    s += __shfl_xor_sync(0xFFFFFFFFu, s, 1);
    s += __shfl_xor_sync(0xFFFFFFFFu, s, 2);
    s += __shfl_xor_sync(0xFFFFFFFFu, s, 4);
    if (part == 0) g_cent2[n] = s;
}

// ---------------- stage 3: build X row-major bf16 hi/lo via smem transpose ----------------
__global__ void buildx_kernel(const float* __restrict__ p0) {
    __shared__ float s[64][65];
    int rt0 = blockIdx.x * 64;
    int kt0 = blockIdx.y * 64;
    int tid = threadIdx.x;
    int rr = tid & 63;
    int r = rt0 + rr;
    int b = r / HWP;
    int pix = r - b * HWP;
    int h = pix / WW, w = pix - h * WW;

    #pragma unroll 1
    for (int i = 0; i < 16; i++) {
        int kk = (tid >> 6) * 16 + i;
        int k = kt0 + kk;
        float val;
        if (k < C0N) {
            const float* p = p0 + (size_t)(b * C0N + k) * HWP;
            float acc = 0.f;
            #pragma unroll
            for (int dy = -1; dy <= 1; dy++) {
                int y = h + dy; if ((unsigned)y >= (unsigned)HH) continue;
                #pragma unroll
                for (int dx = -1; dx <= 1; dx++) {
                    int x = w + dx; if ((unsigned)x >= (unsigned)WW) continue;
                    acc += p[y * WW + x];
                }
            }
            val = acc * (1.f / 9.f);
        } else if (k < C0N + C1N) {
            const float* ch = g_pool1 + (size_t)(b * C1N + (k - C0N)) * 784;
            val = bilin(ch, 28, h * 0.5f - 0.25f, w * 0.5f - 0.25f);
        } else if (k < C0N + C1N + C2N) {
            const float* ch = g_pool2 + (size_t)(b * C2N + (k - C0N - C1N)) * 196;
            val = bilin(ch, 14, h * 0.25f - 0.375f, w * 0.25f - 0.375f);
        } else if (k == 1792) {
            val = (float)h * (2.f / 55.f) - 1.f;
        } else if (k == 1793) {
            val = (float)w * (2.f / 55.f) - 1.f;
        } else {
            val = 0.f;
        }
        s[kk][rr] = val;
    }
    __syncthreads();

    #pragma unroll
    for (int it = 0; it < 2; it++) {
        int sg = tid + it * 256;
        int row = sg >> 3, c8 = (sg & 7) * 8;
        unsigned hw[4], lw[4];
        #pragma unroll
        for (int j = 0; j < 8; j += 2) {
            float v0 = s[c8 + j][row], v1 = s[c8 + j + 1][row];
            unsigned short h0 = f2bf(v0), h1 = f2bf(v1);
            unsigned short l0 = f2bf(v0 - bf2f(h0)), l1 = f2bf(v1 - bf2f(h1));
            hw[j >> 1] = (unsigned)h0 | ((unsigned)h1 << 16);
            lw[j >> 1] = (unsigned)l0 | ((unsigned)l1 << 16);
        }
        size_t base = (size_t)(rt0 + row) * XSTR + kt0 + c8;
        *(uint4*)(gXt + base)       = make_uint4(hw[0], hw[1], hw[2], hw[3]);
        *(uint4*)(gXt + base + KBP) = make_uint4(lw[0], lw[1], lw[2], lw[3]);
    }
}

// ==================================================================
// GEMM-B: phi = X * W^T + bias; fused feat2 + bf16 hi/lo store.
// block 128x64, 8 warps 4m x 2n, warp tile 32x32, cp.async staging.
// ==================================================================
__global__ void __launch_bounds__(256)
gemmB_kernel(const float* __restrict__ bias) {
    using namespace nvcuda;
    extern __shared__ char smc[];
    uint32_t smb = smem_u32(smc);
    const uint32_t Aa[2] = {smb + A0OF, smb + A1OF};
    const uint32_t Ba[2] = {smb + B0OF, smb + B1OF};
    const __nv_bfloat16* Ah[2] = {(const __nv_bfloat16*)(smc + A0OF),
                                  (const __nv_bfloat16*)(smc + A1OF)};
    const __nv_bfloat16* Bh[2] = {(const __nv_bfloat16*)(smc + B0OF),
                                  (const __nv_bfloat16*)(smc + B1OF)};
    float* Cs = (float*)(smc + CSOF);
    float* biasS = (float*)(smc + AUX1);
    float* sfeat = (float*)(smc + AUX2);
    int tid = threadIdx.x, wid = tid >> 5;
    int wm = wid & 3, wn = wid >> 2;
    int r0 = blockIdx.x * 128;
    int erow = tid >> 1, ehalf = tid & 1;
    float feat_acc = 0.f;

    #pragma unroll 1
    for (int nt = 0; nt < DOUT / 64; nt++) {
        if (tid < 64) biasS[tid] = bias[nt * 64 + tid];

        wmma::fragment<wmma::accumulator, 16, 16, 16, float> acc[2][2];
        #pragma unroll
        for (int mi = 0; mi < 2; mi++)
            #pragma unroll
            for (int nj = 0; nj < 2; nj++) wmma::fill_fragment(acc[mi][nj], 0.f);

        auto stage = [&](int c, int buf) {
            int seg = c / SEG_B;
            int kb = (c - seg * SEG_B) * 64;
            int pa = (seg == 2) ? KBP : 0;
            int pb = (seg == 1) ? KBP : 0;
            astage<128>(gXt + (size_t)r0 * XSTR + pa + kb, XSTR, Aa[buf], tid);
            astage<64>(gWt + (size_t)(nt * 64) * XSTR + pb + kb, XSTR, Ba[buf], tid);
        };

        stage(0, 0);
        CP_COMMIT();

        #pragma unroll 1
        for (int c = 0; c < NCH_B; c++) {
            int buf = c & 1;
            if (c + 1 < NCH_B) { stage(c + 1, buf ^ 1); CP_COMMIT(); CP_WAIT1(); }
            else CP_WAIT0();
            __syncthreads();
            const __nv_bfloat16* Ap = Ah[buf];
            const __nv_bfloat16* Bp = Bh[buf];
            #pragma unroll
            for (int ks = 0; ks < 4; ks++) {
                wmma::fragment<wmma::matrix_b, 16, 16, 16, __nv_bfloat16, wmma::col_major> bf[2];
                wmma::load_matrix_sync(bf[0], Bp + (wn * 32) * 72 + ks * 16, 72);
                wmma::load_matrix_sync(bf[1], Bp + (wn * 32 + 16) * 72 + ks * 16, 72);
                #pragma unroll
                for (int mi = 0; mi < 2; mi++) {
                    wmma::fragment<wmma::matrix_a, 16, 16, 16, __nv_bfloat16, wmma::row_major> af;
                    wmma::load_matrix_sync(af, Ap + (wm * 32 + mi * 16) * 72 + ks * 16, 72);
                    wmma::mma_sync(acc[mi][0], af, bf[0], acc[mi][0]);
                    wmma::mma_sync(acc[mi][1], af, bf[1], acc[mi][1]);
                }
            }
            __syncthreads();
        }

        // epilogue through block C tile
        #pragma unroll
        for (int mi = 0; mi < 2; mi++)
            #pragma unroll
            for (int nj = 0; nj < 2; nj++)
                wmma::store_matrix_sync(Cs + (wm * 32 + mi * 16) * 72 + wn * 32 + nj * 16,
                                        acc[mi][nj], 72, wmma::mem_row_major);
        __syncthreads();

        {
            const float* crow = Cs + erow * 72 + ehalf * 32;
            const float* brow = biasS + ehalf * 32;
            size_t r = (size_t)r0 + erow;
            int col0 = nt * 64 + ehalf * 32;
            unsigned hw[16], lw[16];
            #pragma unroll
            for (int j = 0; j < 32; j += 2) {
                float v0 = crow[j] + brow[j];
                float v1 = crow[j + 1] + brow[j + 1];
                feat_acc = fmaf(v0, v0, feat_acc);
                feat_acc = fmaf(v1, v1, feat_acc);
                unsigned short h0 = f2bf(v0), h1 = f2bf(v1);
                unsigned short l0 = f2bf(v0 - bf2f(h0)), l1 = f2bf(v1 - bf2f(h1));
                hw[j >> 1] = (unsigned)h0 | ((unsigned)h1 << 16);
                lw[j >> 1] = (unsigned)l0 | ((unsigned)l1 << 16);
            }
            uint4* dh = (uint4*)(gPhiT + r * PSTR + col0);
            uint4* dl = (uint4*)(gPhiT + r * PSTR + KCP + col0);
            #pragma unroll
            for (int q = 0; q < 4; q++) {
                dh[q] = make_uint4(hw[q * 4], hw[q * 4 + 1], hw[q * 4 + 2], hw[q * 4 + 3]);
                dl[q] = make_uint4(lw[q * 4], lw[q * 4 + 1], lw[q * 4 + 2], lw[q * 4 + 3]);
            }
        }
        __syncthreads();
    }

    if (ehalf == 0) sfeat[erow] = feat_acc;
    __syncthreads();
    if (ehalf == 1) g_feat2[r0 + erow] = sfeat[erow] + feat_acc;
}

// ==================================================================
// GEMM-C: streaming top-3 over 49 center tiles of 64; softmin score.
// block 128x64, 8 warps 4m x 2n, warp tile 32x32, cp.async staging.
// ==================================================================
__global__ void __launch_bounds__(256)
gemmC_kernel(float* __restrict__ out) {
    using namespace nvcuda;
    extern __shared__ char smc[];
    uint32_t smb = smem_u32(smc);
    const uint32_t Aa[2] = {smb + A0OF, smb + A1OF};
    const uint32_t Ba[2] = {smb + B0OF, smb + B1OF};
    const __nv_bfloat16* Ah[2] = {(const __nv_bfloat16*)(smc + A0OF),
                                  (const __nv_bfloat16*)(smc + A1OF)};
    const __nv_bfloat16* Bh[2] = {(const __nv_bfloat16*)(smc + B0OF),
                                  (const __nv_bfloat16*)(smc + B1OF)};
    float* Cs = (float*)(smc + CSOF);
    float* c2S = (float*)(smc + AUX1);
    float* trip = (float*)(smc + AUX2);
    int tid = threadIdx.x, wid = tid >> 5;
    int wm = wid & 3, wn = wid >> 2;
    int r0 = blockIdx.x * 128;
    int erow = tid >> 1, ehalf = tid & 1;

    const float BIG = 3.4e38f;
    float t0 = BIG, t1 = BIG, t2 = BIG;

    #pragma unroll 1
    for (int nt = 0; nt < NC / 64; nt++) {
        if (tid < 64) c2S[tid] = g_cent2[nt * 64 + tid];

        wmma::fragment<wmma::accumulator, 16, 16, 16, float> acc[2][2];
        #pragma unroll
        for (int mi = 0; mi < 2; mi++)
            #pragma unroll
            for (int nj = 0; nj < 2; nj++) wmma::fill_fragment(acc[mi][nj], 0.f);

        auto stage = [&](int c, int buf) {
            int seg = c / SEG_C;
            int kb = (c - seg * SEG_C) * 64;
            int pa = (seg == 2) ? KCP : 0;
            int pb = (seg == 1) ? KCP : 0;
            astage<128>(gPhiT + (size_t)r0 * PSTR + pa + kb, PSTR, Aa[buf], tid);
            astage<64>(gCt + (size_t)(nt * 64) * PSTR + pb + kb, PSTR, Ba[buf], tid);
        };

        stage(0, 0);
        CP_COMMIT();

        #pragma unroll 1
        for (int c = 0; c < NCH_C; c++) {
            int buf = c & 1;
            if (c + 1 < NCH_C) { stage(c + 1, buf ^ 1); CP_COMMIT(); CP_WAIT1(); }
            else CP_WAIT0();
            __syncthreads();
            const __nv_bfloat16* Ap = Ah[buf];
            const __nv_bfloat16* Bp = Bh[buf];
            #pragma unroll
            for (int ks = 0; ks < 4; ks++) {
                wmma::fragment<wmma::matrix_b, 16, 16, 16, __nv_bfloat16, wmma::col_major> bf[2];
                wmma::load_matrix_sync(bf[0], Bp + (wn * 32) * 72 + ks * 16, 72);
                wmma::load_matrix_sync(bf[1], Bp + (wn * 32 + 16) * 72 + ks * 16, 72);
                #pragma unroll
                for (int mi = 0; mi < 2; mi++) {
                    wmma::fragment<wmma::matrix_a, 16, 16, 16, __nv_bfloat16, wmma::row_major> af;
                    wmma::load_matrix_sync(af, Ap + (wm * 32 + mi * 16) * 72 + ks * 16, 72);
                    wmma::mma_sync(acc[mi][0], af, bf[0], acc[mi][0]);
                    wmma::mma_sync(acc[mi][1], af, bf[1], acc[mi][1]);
                }
            }
            __syncthreads();
        }

        #pragma unroll
        for (int mi = 0; mi < 2; mi++)
            #pragma unroll
            for (int nj = 0; nj < 2; nj++)
                wmma::store_matrix_sync(Cs + (wm * 32 + mi * 16) * 72 + wn * 32 + nj * 16,
                                        acc[mi][nj], 72, wmma::mem_row_major);
        __syncthreads();

        {
            const float* crow = Cs + erow * 72 + ehalf * 32;
            const float* c2p = c2S + ehalf * 32;
            #pragma unroll
            for (int j = 0; j < 32; j++) {
                float key = c2p[j] - 2.f * crow[j];
                ins3(key, t0, t1, t2);
            }
        }
        __syncthreads();
    }

    // merge halves
    if (ehalf == 0) {
        trip[erow * 3 + 0] = t0;
        trip[erow * 3 + 1] = t1;
        trip[erow * 3 + 2] = t2;
    }
    __syncthreads();
    if (ehalf == 1) {
        ins3(trip[erow * 3 + 0], t0, t1, t2);
        ins3(trip[erow * 3 + 1], t0, t1, t2);
        ins3(trip[erow * 3 + 2], t0, t1, t2);
        float f2 = g_feat2[r0 + erow];
        float d0 = sqrtf(fmaxf(f2 + t0, 0.f));
        float d1 = sqrtf(fmaxf(f2 + t1, 0.f));
        float d2 = sqrtf(fmaxf(f2 + t2, 0.f));
        float s = 1.f / (1.f + expf(d0 - d1) + expf(d0 - d2));
        out[r0 + erow] = d0 * s;
    }
}

// ---------------- launch ----------------
extern "C" void kernel_launch(void* const* d_in, const int* in_sizes, int n_in,
                              void* d_out, int out_size) {
    (void)in_sizes; (void)n_in; (void)out_size;
    const float* p0     = (const float*)d_in[0];
    const float* p1     = (const float*)d_in[1];
    const float* p2     = (const float*)d_in[2];
    const float* conv_w = (const float*)d_in[3];
    const float* conv_b = (const float*)d_in[4];
    const float* Cmat   = (const float*)d_in[5];
    float* out = (float*)d_out;

    {
        int t1 = BZ * C1N * 28 * 28;
        pool_kernel<<<(t1 + 255) / 256, 256>>>(p1, t1, 28, 0);
        int t2 = BZ * C2N * 14 * 14;
        pool_kernel<<<(t2 + 255) / 256, 256>>>(p2, t2, 14, 1);
    }
    prepW_kernel<<<(DOUT * KBP + 255) / 256, 256>>>(conv_w);
    prepC_kernel<<<(NC * KCP + 255) / 256, 256>>>(Cmat);
    cent2_kernel<<<(NC * 8 + 255) / 256, 256>>>(Cmat);
    {
        dim3 grid(RR / 64, KBP / 64);
        buildx_kernel<<<grid, 256>>>(p0);
    }
    {
        cudaFuncSetAttribute(gemmB_kernel, cudaFuncAttributeMaxDynamicSharedMemorySize, SMEM_SZ);
        gemmB_kernel<<<RR / 128, 256, SMEM_SZ>>>(conv_b);
    }
    {
        cudaFuncSetAttribute(gemmC_kernel, cudaFuncAttributeMaxDynamicSharedMemorySize, SMEM_SZ);
        gemmC_kernel<<<RR / 128, 256, SMEM_SZ>>>(out);
    }
}